// round 6
// baseline (speedup 1.0000x reference)
#include <cuda_runtime.h>
#include <math.h>

#define BB 4
#define SS 1024
#define DM 1280
#define NH 16
#define DK 80
#define GR 5
#define CPG 256

// ---- scratch (device globals; no allocations allowed) ----
__device__ float g_q[(size_t)BB*NH*SS*DK];
__device__ float g_k[(size_t)BB*NH*SS*DK];
__device__ float g_v[(size_t)BB*NH*SS*DK];
__device__ float g_att[(size_t)BB*SS*DM];

// ---- helpers ----
__device__ __forceinline__ float f2tf32(float x) {
    unsigned u;
    asm("cvt.rna.tf32.f32 %0, %1;" : "=r"(u) : "f"(x));
    return __uint_as_float(u);
}
__device__ __forceinline__ void mma_tf32(float d[4], const unsigned a[4], const unsigned b[2]) {
    asm volatile(
        "mma.sync.aligned.m16n8k8.row.col.f32.tf32.tf32.f32 "
        "{%0,%1,%2,%3}, {%4,%5,%6,%7}, {%8,%9}, {%0,%1,%2,%3};\n"
        : "+f"(d[0]), "+f"(d[1]), "+f"(d[2]), "+f"(d[3])
        : "r"(a[0]), "r"(a[1]), "r"(a[2]), "r"(a[3]), "r"(b[0]), "r"(b[1]));
}
__device__ __forceinline__ void mma_bf16(float d[4], const unsigned a[4], const unsigned b[2]) {
    asm volatile(
        "mma.sync.aligned.m16n8k16.row.col.f32.bf16.bf16.f32 "
        "{%0,%1,%2,%3}, {%4,%5,%6,%7}, {%8,%9}, {%0,%1,%2,%3};\n"
        : "+f"(d[0]), "+f"(d[1]), "+f"(d[2]), "+f"(d[3])
        : "r"(a[0]), "r"(a[1]), "r"(a[2]), "r"(a[3]), "r"(b[0]), "r"(b[1]));
}
__device__ __forceinline__ unsigned pack_bf16(float hi, float lo) {
    unsigned r;
    asm("cvt.rn.bf16x2.f32 %0, %1, %2;" : "=r"(r) : "f"(hi), "f"(lo));
    return r;
}
__device__ __forceinline__ float bf_lo(unsigned w) { return __uint_as_float(w << 16); }
__device__ __forceinline__ float bf_hi(unsigned w) { return __uint_as_float(w & 0xffff0000u); }

__device__ __forceinline__ unsigned smem_u32(const void* p) {
    return (unsigned)__cvta_generic_to_shared(p);
}
__device__ __forceinline__ void cp16(unsigned s, const void* g) {
    asm volatile("cp.async.cg.shared.global [%0], [%1], 16;" :: "r"(s), "l"(g));
}
__device__ __forceinline__ void cp_commit() { asm volatile("cp.async.commit_group;"); }
template<int N> __device__ __forceinline__ void cp_wait() {
    asm volatile("cp.async.wait_group %0;" :: "n"(N));
}
// column pairing within 8-group: (t, t+4) -> adjacent (2t, 2t+1)
__device__ __forceinline__ int perm8(int c) {
    return (c & ~7) | ((c & 3) << 1) | ((c >> 2) & 1);
}

// ============================================================
// Kernel 1: channel shuffle + per-head QKV projections
// (unchanged from round 5 — 49us)
// ============================================================
#define XS 84
#define QKV_SMEM_FLOATS (128*XS + 80*XS + 80)

__global__ __launch_bounds__(256) void qkv_kernel(
    const float* __restrict__ src,
    const float* __restrict__ Wq, const float* __restrict__ bq,
    const float* __restrict__ Wk, const float* __restrict__ bk,
    const float* __restrict__ Wv, const float* __restrict__ bv)
{
    extern __shared__ float qsm[];
    float* sX = qsm;              // [128][84]
    float* sW = sX + 128*XS;      // [80][84]
    float* sb = sW + 80*XS;       // [80]

    const int b = blockIdx.z, h = blockIdx.y, s0 = blockIdx.x * 128;
    const int tid = threadIdx.x;
    const int warp = tid >> 5, lane = tid & 31;
    const int g = lane >> 2, t = lane & 3;
    const int wr = warp * 16;

    #pragma unroll
    for (int p = 0; p < 10; p++) {
        int idx = tid + p*256;
        int r = idx / 20, q = idx % 20;
        int j = q / 4, m = q % 4;
        float4 v = *(const float4*)&src[((size_t)b*SS + s0 + r)*DM + j*CPG + 16*h + m*4];
        int kbase = (m*4)*5 + j;
        sX[r*XS + kbase     ] = f2tf32(v.x);
        sX[r*XS + kbase + 5 ] = f2tf32(v.y);
        sX[r*XS + kbase + 10] = f2tf32(v.z);
        sX[r*XS + kbase + 15] = f2tf32(v.w);
    }
    __syncthreads();

    unsigned qa[10][4];
    #pragma unroll
    for (int ks = 0; ks < 10; ks++) {
        qa[ks][0] = __float_as_uint(sX[(wr + g    )*XS + ks*8 + t    ]);
        qa[ks][1] = __float_as_uint(sX[(wr + g + 8)*XS + ks*8 + t    ]);
        qa[ks][2] = __float_as_uint(sX[(wr + g    )*XS + ks*8 + t + 4]);
        qa[ks][3] = __float_as_uint(sX[(wr + g + 8)*XS + ks*8 + t + 4]);
    }

    const float* Ws[3] = {Wq, Wk, Wv};
    const float* bs[3] = {bq, bk, bv};
    float* outs[3] = {g_q, g_k, g_v};

    for (int pj = 0; pj < 3; pj++) {
        __syncthreads();
        for (int i = tid; i < 1600; i += 256) {
            int e = i / 20, k = (i % 20) * 4;
            float4 w = *(const float4*)&Ws[pj][h*DK*DK + e*DK + k];
            float4 wr4 = make_float4(f2tf32(w.x), f2tf32(w.y), f2tf32(w.z), f2tf32(w.w));
            *(float4*)&sW[e*XS + k] = wr4;
        }
        if (tid < DK) sb[tid] = bs[pj][h*DK + tid];
        __syncthreads();

        float acc[10][4];
        #pragma unroll
        for (int nt = 0; nt < 10; nt++)
            #pragma unroll
            for (int j = 0; j < 4; j++) acc[nt][j] = 0.f;

        #pragma unroll
        for (int ks = 0; ks < 10; ks++) {
            #pragma unroll
            for (int nt = 0; nt < 10; nt++) {
                unsigned bb[2];
                bb[0] = __float_as_uint(sW[(nt*8 + g)*XS + ks*8 + t    ]);
                bb[1] = __float_as_uint(sW[(nt*8 + g)*XS + ks*8 + t + 4]);
                mma_tf32(acc[nt], qa[ks], bb);
            }
        }

        float* outp = outs[pj] + (((size_t)b*NH + h)*SS + s0) * DK;
        #pragma unroll
        for (int nt = 0; nt < 10; nt++) {
            int c = nt*8 + 2*t;
            float b0 = sb[c], b1 = sb[c + 1];
            float2 v0 = make_float2(f2tf32(acc[nt][0] + b0), f2tf32(acc[nt][1] + b1));
            float2 v1 = make_float2(f2tf32(acc[nt][2] + b0), f2tf32(acc[nt][3] + b1));
            *(float2*)&outp[(size_t)(wr + g    )*DK + c] = v0;
            *(float2*)&outp[(size_t)(wr + g + 8)*DK + c] = v1;
        }
    }
}

// ============================================================
// Kernel 2: flash attention, tf32 mma, 4 warps x 32 q-rows
// K/V B-fragments amortized over 2 m-tiles -> tensor-bound
// ============================================================
#define AT_THREADS 128
#define QP 88
#define KP 84
#define VP 88
#define PPW 72
#define OFF_Q 0
#define OFF_K (128*QP)
#define OFF_V (OFF_K + 2*64*KP)
#define OFF_P (OFF_V + 2*64*VP)
#define ATTN_SMEM_FLOATS (OFF_P + 4*32*PPW)

__device__ __forceinline__ void attn_issue(const float* Kb, const float* Vb,
                                           float* sK, float* sV, int kt, int tid)
{
    #pragma unroll
    for (int p = 0; p < 10; p++) {
        int c = tid + p*AT_THREADS;
        int r = c / 20, seg = c % 20;
        cp16(smem_u32(sK + r*KP + seg*4), Kb + (size_t)(kt + r)*DK + seg*4);
    }
    #pragma unroll
    for (int p = 0; p < 10; p++) {
        int c = tid + p*AT_THREADS;
        int r = c / 20, seg = c % 20;
        cp16(smem_u32(sV + r*VP + seg*4), Vb + (size_t)(kt + r)*DK + seg*4);
    }
    cp_commit();
}

__global__ __launch_bounds__(AT_THREADS) void attn_kernel()
{
    extern __shared__ float sm[];
    float* sQ = sm + OFF_Q;

    const int b = blockIdx.z, h = blockIdx.y, q0 = blockIdx.x * 128;
    const int tid = threadIdx.x;
    const int warp = tid >> 5, lane = tid & 31;
    const int g = lane >> 2, t = lane & 3;
    const int wr = warp * 32;
    float* sP = sm + OFF_P + warp * 32 * PPW;   // warp-private

    const size_t base = ((size_t)b*NH + h) * SS * DK;
    const float* Qb = g_q + base;
    const float* Kb = g_k + base;
    const float* Vb = g_v + base;

    const float scl = rsqrtf((float)DK);

    // stage Q (scaled, rna, column-paired): 2560 float4 pieces
    #pragma unroll
    for (int p = 0; p < 20; p++) {
        int idx = tid + p*AT_THREADS;
        int r = idx / 20, q4 = idx % 20;
        float4 v = *(const float4*)&Qb[(size_t)(q0 + r)*DK + q4*4];
        int k = q4*4;
        sQ[r*QP + perm8(k    )] = f2tf32(v.x * scl);
        sQ[r*QP + perm8(k + 1)] = f2tf32(v.y * scl);
        sQ[r*QP + perm8(k + 2)] = f2tf32(v.z * scl);
        sQ[r*QP + perm8(k + 3)] = f2tf32(v.w * scl);
    }
    attn_issue(Kb, Vb, sm + OFF_K, sm + OFF_V, 0, tid);
    __syncthreads();

    float O[2][10][4];
    #pragma unroll
    for (int mt = 0; mt < 2; mt++)
        #pragma unroll
        for (int nt = 0; nt < 10; nt++)
            #pragma unroll
            for (int j = 0; j < 4; j++) O[mt][nt][j] = 0.f;
    float mM[2][2], lL[2][2];
    #pragma unroll
    for (int mt = 0; mt < 2; mt++) {
        mM[mt][0] = mM[mt][1] = -1e30f;
        lL[mt][0] = lL[mt][1] = 0.f;
    }

    const int pc0 = ((2*t & 3) << 1) | ((2*t) >> 2);
    const int pc1 = (((2*t+1) & 3) << 1) | ((2*t+1) >> 2);

    for (int tt = 0; tt < SS/64; tt++) {
        float* sK = sm + OFF_K + (tt & 1) * 64*KP;
        float* sV = sm + OFF_V + (tt & 1) * 64*VP;

        if (tt + 1 < SS/64) {
            attn_issue(Kb, Vb, sm + OFF_K + ((tt+1)&1)*64*KP,
                       sm + OFF_V + ((tt+1)&1)*64*VP, (tt+1)*64, tid);
            cp_wait<1>();
        } else {
            cp_wait<0>();
        }
        __syncthreads();

        // ---- scores: 32x64 per warp, shared K B-frags across 2 m-tiles ----
        float sc[2][8][4];
        #pragma unroll
        for (int mt = 0; mt < 2; mt++)
            #pragma unroll
            for (int nt = 0; nt < 8; nt++)
                #pragma unroll
                for (int j = 0; j < 4; j++) sc[mt][nt][j] = 0.f;

        #pragma unroll
        for (int ks = 0; ks < 10; ks++) {
            unsigned qa2[2][4];
            #pragma unroll
            for (int mt = 0; mt < 2; mt++) {
                float2 qlo = *(const float2*)&sQ[(wr + mt*16 + g    )*QP + ks*8 + 2*t];
                float2 qhi = *(const float2*)&sQ[(wr + mt*16 + g + 8)*QP + ks*8 + 2*t];
                qa2[mt][0] = __float_as_uint(qlo.x);
                qa2[mt][2] = __float_as_uint(qlo.y);
                qa2[mt][1] = __float_as_uint(qhi.x);
                qa2[mt][3] = __float_as_uint(qhi.y);
            }
            #pragma unroll
            for (int nt = 0; nt < 8; nt++) {
                unsigned bb[2];
                bb[0] = __float_as_uint(sK[(nt*8 + g)*KP + ks*8 + t    ]);
                bb[1] = __float_as_uint(sK[(nt*8 + g)*KP + ks*8 + t + 4]);
                mma_tf32(sc[0][nt], qa2[0], bb);
                mma_tf32(sc[1][nt], qa2[1], bb);
            }
        }

        // ---- online softmax + stage P, per m-tile ----
        #pragma unroll
        for (int mt = 0; mt < 2; mt++) {
            float mx0 = -1e30f, mx1 = -1e30f;
            #pragma unroll
            for (int nt = 0; nt < 8; nt++) {
                mx0 = fmaxf(mx0, fmaxf(sc[mt][nt][0], sc[mt][nt][1]));
                mx1 = fmaxf(mx1, fmaxf(sc[mt][nt][2], sc[mt][nt][3]));
            }
            #pragma unroll
            for (int msk = 1; msk <= 2; msk <<= 1) {
                mx0 = fmaxf(mx0, __shfl_xor_sync(0xffffffffu, mx0, msk));
                mx1 = fmaxf(mx1, __shfl_xor_sync(0xffffffffu, mx1, msk));
            }
            float mn0 = fmaxf(mM[mt][0], mx0), mn1 = fmaxf(mM[mt][1], mx1);
            float a0 = __expf(mM[mt][0] - mn0), a1 = __expf(mM[mt][1] - mn1);
            mM[mt][0] = mn0; mM[mt][1] = mn1;

            float sum0 = 0.f, sum1 = 0.f;
            #pragma unroll
            for (int nt = 0; nt < 8; nt++) {
                sc[mt][nt][0] = __expf(sc[mt][nt][0] - mn0);
                sc[mt][nt][1] = __expf(sc[mt][nt][1] - mn0);
                sc[mt][nt][2] = __expf(sc[mt][nt][2] - mn1);
                sc[mt][nt][3] = __expf(sc[mt][nt][3] - mn1);
                sum0 += sc[mt][nt][0] + sc[mt][nt][1];
                sum1 += sc[mt][nt][2] + sc[mt][nt][3];
            }
            #pragma unroll
            for (int msk = 1; msk <= 2; msk <<= 1) {
                sum0 += __shfl_xor_sync(0xffffffffu, sum0, msk);
                sum1 += __shfl_xor_sync(0xffffffffu, sum1, msk);
            }
            lL[mt][0] = lL[mt][0]*a0 + sum0;
            lL[mt][1] = lL[mt][1]*a1 + sum1;

            #pragma unroll
            for (int nt = 0; nt < 10; nt++) {
                O[mt][nt][0] *= a0; O[mt][nt][1] *= a0;
                O[mt][nt][2] *= a1; O[mt][nt][3] *= a1;
            }

            #pragma unroll
            for (int nt = 0; nt < 8; nt++) {
                sP[(mt*16 + g    )*PPW + nt*8 + pc0] = f2tf32(sc[mt][nt][0]);
                sP[(mt*16 + g    )*PPW + nt*8 + pc1] = f2tf32(sc[mt][nt][1]);
                sP[(mt*16 + g + 8)*PPW + nt*8 + pc0] = f2tf32(sc[mt][nt][2]);
                sP[(mt*16 + g + 8)*PPW + nt*8 + pc1] = f2tf32(sc[mt][nt][3]);
            }
        }
        __syncwarp();

        // ---- PV: O(32x80) += P(32x64) @ V(64x80), shared V B-frags ----
        #pragma unroll
        for (int ks = 0; ks < 8; ks++) {
            unsigned pa[2][4];
            #pragma unroll
            for (int mt = 0; mt < 2; mt++) {
                float2 plo = *(const float2*)&sP[(mt*16 + g    )*PPW + ks*8 + 2*t];
                float2 phi = *(const float2*)&sP[(mt*16 + g + 8)*PPW + ks*8 + 2*t];
                pa[mt][0] = __float_as_uint(plo.x);
                pa[mt][2] = __float_as_uint(plo.y);
                pa[mt][1] = __float_as_uint(phi.x);
                pa[mt][3] = __float_as_uint(phi.y);
            }
            #pragma unroll
            for (int nt = 0; nt < 10; nt++) {
                unsigned bb[2];
                bb[0] = __float_as_uint(sV[(ks*8 + t    )*VP + nt*8 + g]);
                bb[1] = __float_as_uint(sV[(ks*8 + t + 4)*VP + nt*8 + g]);
                mma_tf32(O[0][nt], pa[0], bb);
                mma_tf32(O[1][nt], pa[1], bb);
            }
        }
        __syncthreads();
    }

    // ---- epilogue ----
    #pragma unroll
    for (int mt = 0; mt < 2; mt++) {
        float inv0 = 1.f / lL[mt][0], inv1 = 1.f / lL[mt][1];
        int s0r = q0 + wr + mt*16 + g, s1r = s0r + 8;
        #pragma unroll
        for (int nt = 0; nt < 10; nt++) {
            int c = nt*8 + 2*t;
            float2 v0 = make_float2(O[mt][nt][0]*inv0, O[mt][nt][1]*inv0);
            float2 v1 = make_float2(O[mt][nt][2]*inv1, O[mt][nt][3]*inv1);
            *(float2*)&g_att[((size_t)b*SS + s0r)*DM + h*DK + c] = v0;
            *(float2*)&g_att[((size_t)b*SS + s1r)*DM + h*DK + c] = v1;
        }
    }
}

// ============================================================
// Kernel 3: out = g_att @ Wo^T + bo, bf16 3-term split
// (unchanged from round 5)
// ============================================================
#define GWS 12
#define GBUF (128*GWS)
#define GEMM_SMEM_U32 (8*GBUF)

__global__ __launch_bounds__(256, 2) void out_gemm(
    const float* __restrict__ Wo, const float* __restrict__ bo,
    float* __restrict__ out)
{
    extern __shared__ unsigned gsm[];
    unsigned* AH = gsm;
    unsigned* AL = gsm + 2*GBUF;
    unsigned* BH = gsm + 4*GBUF;
    unsigned* BL = gsm + 6*GBUF;

    const int m0 = blockIdx.y * 128, n0 = blockIdx.x * 128;
    const int tid = threadIdx.x;
    const int warp = tid >> 5, lane = tid & 31;
    const int g = lane >> 2, t = lane & 3;
    const int wm = warp >> 2, wn = warp & 3;

    const int ar0 = tid >> 2, ar1 = (tid + 256) >> 2;
    const int ac = (tid & 3) * 4;
    const int w0 = (tid & 3) * 2;
    const int pw0 = perm8(w0), pw1 = perm8(w0 + 1);

    float acc[4][4][4];
    #pragma unroll
    for (int mt = 0; mt < 4; mt++)
        #pragma unroll
        for (int nt = 0; nt < 4; nt++)
            #pragma unroll
            for (int j = 0; j < 4; j++) acc[mt][nt][j] = 0.f;

    float4 ra[2], rb[2];
    ra[0] = *(const float4*)&g_att[(size_t)(m0 + ar0)*DM + ac];
    ra[1] = *(const float4*)&g_att[(size_t)(m0 + ar1)*DM + ac];
    rb[0] = *(const float4*)&Wo[(size_t)(n0 + ar0)*DM + ac];
    rb[1] = *(const float4*)&Wo[(size_t)(n0 + ar1)*DM + ac];

    for (int kc = 0; kc < DM/16; kc++) {
        const int bs = kc & 1;
        unsigned* ah = AH + bs*GBUF;
        unsigned* al = AL + bs*GBUF;
        unsigned* bh = BH + bs*GBUF;
        unsigned* bl = BL + bs*GBUF;

        #pragma unroll
        for (int p = 0; p < 2; p++) {
            int r = p ? ar1 : ar0;
            float4 va = ra[p], vb = rb[p];
            unsigned ha0 = pack_bf16(va.y, va.x);
            unsigned ha1 = pack_bf16(va.w, va.z);
            unsigned la0 = pack_bf16(va.y - bf_hi(ha0), va.x - bf_lo(ha0));
            unsigned la1 = pack_bf16(va.w - bf_hi(ha1), va.z - bf_lo(ha1));
            ah[r*GWS + pw0] = ha0;  ah[r*GWS + pw1] = ha1;
            al[r*GWS + pw0] = la0;  al[r*GWS + pw1] = la1;
            unsigned hb0 = pack_bf16(vb.y, vb.x);
            unsigned hb1 = pack_bf16(vb.w, vb.z);
            unsigned lb0 = pack_bf16(vb.y - bf_hi(hb0), vb.x - bf_lo(hb0));
            unsigned lb1 = pack_bf16(vb.w - bf_hi(hb1), vb.z - bf_lo(hb1));
            bh[r*GWS + pw0] = hb0;  bh[r*GWS + pw1] = hb1;
            bl[r*GWS + pw0] = lb0;  bl[r*GWS + pw1] = lb1;
        }

        if (kc + 1 < DM/16) {
            int k0n = (kc + 1) * 16;
            ra[0] = *(const float4*)&g_att[(size_t)(m0 + ar0)*DM + k0n + ac];
            ra[1] = *(const float4*)&g_att[(size_t)(m0 + ar1)*DM + k0n + ac];
            rb[0] = *(const float4*)&Wo[(size_t)(n0 + ar0)*DM + k0n + ac];
            rb[1] = *(const float4*)&Wo[(size_t)(n0 + ar1)*DM + k0n + ac];
        }
        __syncthreads();

        unsigned fbh[4][2], fbl[4][2];
        #pragma unroll
        for (int nt = 0; nt < 4; nt++) {
            int br = wn*32 + nt*8 + g;
            uint2 xh = *(const uint2*)&bh[br*GWS + 2*t];
            uint2 xl = *(const uint2*)&bl[br*GWS + 2*t];
            fbh[nt][0] = xh.x; fbh[nt][1] = xh.y;
            fbl[nt][0] = xl.x; fbl[nt][1] = xl.y;
        }
        #pragma unroll
        for (int mt = 0; mt < 4; mt++) {
            int mr = wm*64 + mt*16 + g;
            uint2 alo = *(const uint2*)&ah[ mr     *GWS + 2*t];
            uint2 ahi = *(const uint2*)&ah[(mr + 8)*GWS + 2*t];
            uint2 llo = *(const uint2*)&al[ mr     *GWS + 2*t];
            uint2 lhi = *(const uint2*)&al[(mr + 8)*GWS + 2*t];
            unsigned fah[4] = {alo.x, ahi.x, alo.y, ahi.y};
            unsigned fal[4] = {llo.x, lhi.x, llo.y, lhi.y};
            #pragma unroll
            for (int nt = 0; nt < 4; nt++) {
                mma_bf16(acc[mt][nt], fah, fbh[nt]);
                mma_bf16(acc[mt][nt], fah, fbl[nt]);
                mma_bf16(acc[mt][nt], fal, fbh[nt]);
            }
        }
    }

    #pragma unroll
    for (int mt = 0; mt < 4; mt++) {
        int r0 = m0 + wm*64 + mt*16 + g;
        #pragma unroll
        for (int nt = 0; nt < 4; nt++) {
            int c0 = n0 + wn*32 + nt*8 + 2*t;
            float2 b2 = *(const float2*)&bo[c0];
            float2 v0 = make_float2(acc[mt][nt][0] + b2.x, acc[mt][nt][1] + b2.y);
            float2 v1 = make_float2(acc[mt][nt][2] + b2.x, acc[mt][nt][3] + b2.y);
            *(float2*)&out[(size_t)r0*DM + c0] = v0;
            *(float2*)&out[(size_t)(r0 + 8)*DM + c0] = v1;
        }
    }
}

// ============================================================
extern "C" void kernel_launch(void* const* d_in, const int* in_sizes, int n_in,
                              void* d_out, int out_size)
{
    const float* src = (const float*)d_in[0];
    const float* Wq = (const float*)d_in[3];
    const float* bq = (const float*)d_in[4];
    const float* Wk = (const float*)d_in[5];
    const float* bk = (const float*)d_in[6];
    const float* Wv = (const float*)d_in[7];
    const float* bv = (const float*)d_in[8];
    const float* Wo = (const float*)d_in[9];
    const float* bo = (const float*)d_in[10];
    float* out = (float*)d_out;

    const int smem_qkv  = QKV_SMEM_FLOATS * (int)sizeof(float);
    const int smem_attn = ATTN_SMEM_FLOATS * (int)sizeof(float);
    const int smem_gemm = GEMM_SMEM_U32 * (int)sizeof(unsigned);
    cudaFuncSetAttribute(qkv_kernel, cudaFuncAttributeMaxDynamicSharedMemorySize, smem_qkv);
    cudaFuncSetAttribute(attn_kernel, cudaFuncAttributeMaxDynamicSharedMemorySize, smem_attn);
    cudaFuncSetAttribute(out_gemm, cudaFuncAttributeMaxDynamicSharedMemorySize, smem_gemm);

    qkv_kernel<<<dim3(SS/128, NH, BB), 256, smem_qkv>>>(src, Wq, bq, Wk, bk, Wv, bv);
    attn_kernel<<<dim3(SS/128, NH, BB), AT_THREADS, smem_attn>>>();
    out_gemm<<<dim3(DM/128, (BB*SS)/128), 256, smem_gemm>>>(Wo, bo, out);
}

// round 7
// speedup vs baseline: 1.0561x; 1.0561x over previous
#include <cuda_runtime.h>
#include <math.h>

#define BB 4
#define SS 1024
#define DM 1280
#define NH 16
#define DK 80
#define GR 5
#define CPG 256

// ---- scratch (device globals; no allocations allowed) ----
__device__ float g_q[(size_t)BB*NH*SS*DK];
__device__ float g_k[(size_t)BB*NH*SS*DK];
__device__ float g_v[(size_t)BB*NH*SS*DK];
__device__ float g_att[(size_t)BB*SS*DM];

// ---- helpers ----
__device__ __forceinline__ float f2tf32(float x) {
    unsigned u;
    asm("cvt.rna.tf32.f32 %0, %1;" : "=r"(u) : "f"(x));
    return __uint_as_float(u);
}
__device__ __forceinline__ void mma_tf32(float d[4], const unsigned a[4], const unsigned b[2]) {
    asm volatile(
        "mma.sync.aligned.m16n8k8.row.col.f32.tf32.tf32.f32 "
        "{%0,%1,%2,%3}, {%4,%5,%6,%7}, {%8,%9}, {%0,%1,%2,%3};\n"
        : "+f"(d[0]), "+f"(d[1]), "+f"(d[2]), "+f"(d[3])
        : "r"(a[0]), "r"(a[1]), "r"(a[2]), "r"(a[3]), "r"(b[0]), "r"(b[1]));
}
__device__ __forceinline__ void mma_bf16(float d[4], const unsigned a[4], const unsigned b[2]) {
    asm volatile(
        "mma.sync.aligned.m16n8k16.row.col.f32.bf16.bf16.f32 "
        "{%0,%1,%2,%3}, {%4,%5,%6,%7}, {%8,%9}, {%0,%1,%2,%3};\n"
        : "+f"(d[0]), "+f"(d[1]), "+f"(d[2]), "+f"(d[3])
        : "r"(a[0]), "r"(a[1]), "r"(a[2]), "r"(a[3]), "r"(b[0]), "r"(b[1]));
}
__device__ __forceinline__ unsigned pack_bf16(float hi, float lo) {
    unsigned r;
    asm("cvt.rn.bf16x2.f32 %0, %1, %2;" : "=r"(r) : "f"(hi), "f"(lo));
    return r;
}
__device__ __forceinline__ float bf_lo(unsigned w) { return __uint_as_float(w << 16); }
__device__ __forceinline__ float bf_hi(unsigned w) { return __uint_as_float(w & 0xffff0000u); }

__device__ __forceinline__ unsigned smem_u32(const void* p) {
    return (unsigned)__cvta_generic_to_shared(p);
}
__device__ __forceinline__ void cp16(unsigned s, const void* g) {
    asm volatile("cp.async.cg.shared.global [%0], [%1], 16;" :: "r"(s), "l"(g));
}
__device__ __forceinline__ void cp_commit() { asm volatile("cp.async.commit_group;"); }
template<int N> __device__ __forceinline__ void cp_wait() {
    asm volatile("cp.async.wait_group %0;" :: "n"(N));
}
// column pairing within 8-group: (t, t+4) -> adjacent (2t, 2t+1)
__device__ __forceinline__ int perm8(int c) {
    return (c & ~7) | ((c & 3) << 1) | ((c >> 2) & 1);
}

// ============================================================
// Kernel 1: channel shuffle + per-head QKV projections
// (round-5 version; q projection now pre-scaled by 1/sqrt(dk))
// ============================================================
#define XS 84
#define QKV_SMEM_FLOATS (128*XS + 80*XS + 80)

__global__ __launch_bounds__(256) void qkv_kernel(
    const float* __restrict__ src,
    const float* __restrict__ Wq, const float* __restrict__ bq,
    const float* __restrict__ Wk, const float* __restrict__ bk,
    const float* __restrict__ Wv, const float* __restrict__ bv)
{
    extern __shared__ float qsm[];
    float* sX = qsm;              // [128][84]
    float* sW = sX + 128*XS;      // [80][84]
    float* sb = sW + 80*XS;       // [80]

    const int b = blockIdx.z, h = blockIdx.y, s0 = blockIdx.x * 128;
    const int tid = threadIdx.x;
    const int warp = tid >> 5, lane = tid & 31;
    const int g = lane >> 2, t = lane & 3;
    const int wr = warp * 16;

    #pragma unroll
    for (int p = 0; p < 10; p++) {
        int idx = tid + p*256;
        int r = idx / 20, q = idx % 20;
        int j = q / 4, m = q % 4;
        float4 v = *(const float4*)&src[((size_t)b*SS + s0 + r)*DM + j*CPG + 16*h + m*4];
        int kbase = (m*4)*5 + j;
        sX[r*XS + kbase     ] = f2tf32(v.x);
        sX[r*XS + kbase + 5 ] = f2tf32(v.y);
        sX[r*XS + kbase + 10] = f2tf32(v.z);
        sX[r*XS + kbase + 15] = f2tf32(v.w);
    }
    __syncthreads();

    unsigned qa[10][4];
    #pragma unroll
    for (int ks = 0; ks < 10; ks++) {
        qa[ks][0] = __float_as_uint(sX[(wr + g    )*XS + ks*8 + t    ]);
        qa[ks][1] = __float_as_uint(sX[(wr + g + 8)*XS + ks*8 + t    ]);
        qa[ks][2] = __float_as_uint(sX[(wr + g    )*XS + ks*8 + t + 4]);
        qa[ks][3] = __float_as_uint(sX[(wr + g + 8)*XS + ks*8 + t + 4]);
    }

    const float* Ws[3] = {Wq, Wk, Wv};
    const float* bs[3] = {bq, bk, bv};
    float* outs[3] = {g_q, g_k, g_v};
    const float scl = rsqrtf((float)DK);

    for (int pj = 0; pj < 3; pj++) {
        const float s = (pj == 0) ? scl : 1.f;   // fold 1/sqrt(dk) into Q
        __syncthreads();
        for (int i = tid; i < 1600; i += 256) {
            int e = i / 20, k = (i % 20) * 4;
            float4 w = *(const float4*)&Ws[pj][h*DK*DK + e*DK + k];
            float4 wr4 = make_float4(f2tf32(w.x*s), f2tf32(w.y*s), f2tf32(w.z*s), f2tf32(w.w*s));
            *(float4*)&sW[e*XS + k] = wr4;
        }
        if (tid < DK) sb[tid] = bs[pj][h*DK + tid] * s;
        __syncthreads();

        float acc[10][4];
        #pragma unroll
        for (int nt = 0; nt < 10; nt++)
            #pragma unroll
            for (int j = 0; j < 4; j++) acc[nt][j] = 0.f;

        #pragma unroll
        for (int ks = 0; ks < 10; ks++) {
            #pragma unroll
            for (int nt = 0; nt < 10; nt++) {
                unsigned bb[2];
                bb[0] = __float_as_uint(sW[(nt*8 + g)*XS + ks*8 + t    ]);
                bb[1] = __float_as_uint(sW[(nt*8 + g)*XS + ks*8 + t + 4]);
                mma_tf32(acc[nt], qa[ks], bb);
            }
        }

        float* outp = outs[pj] + (((size_t)b*NH + h)*SS + s0) * DK;
        #pragma unroll
        for (int nt = 0; nt < 10; nt++) {
            int c = nt*8 + 2*t;
            float b0 = sb[c], b1 = sb[c + 1];
            float2 v0 = make_float2(f2tf32(acc[nt][0] + b0), f2tf32(acc[nt][1] + b1));
            float2 v1 = make_float2(f2tf32(acc[nt][2] + b0), f2tf32(acc[nt][3] + b1));
            *(float2*)&outp[(size_t)(wr + g    )*DK + c] = v0;
            *(float2*)&outp[(size_t)(wr + g + 8)*DK + c] = v1;
        }
    }
}

// ============================================================
// Kernel 2: flash attention, tf32 mma, 8 warps x 16 q-rows
// occ 2: no sQ (Q frags from gmem, pre-scaled/rounded by qkv),
// K single-buffered, V double-buffered, per-warp P region.
// ============================================================
#define KP 84
#define VP 88
#define PPW 72
#define A_OFF_K 0
#define A_OFF_V (64*KP)
#define A_OFF_P (A_OFF_V + 2*64*VP)
#define ATTN_SMEM_FLOATS (A_OFF_P + 8*16*PPW)

__device__ __forceinline__ void issueK(const float* Kb, float* sK, int kt, int tid)
{
    #pragma unroll
    for (int p = 0; p < 5; p++) {
        int c = tid + p*256;
        int r = c / 20, seg = c % 20;
        cp16(smem_u32(sK + r*KP + seg*4), Kb + (size_t)(kt + r)*DK + seg*4);
    }
    cp_commit();
}
__device__ __forceinline__ void issueV(const float* Vb, float* sV, int kt, int tid)
{
    #pragma unroll
    for (int p = 0; p < 5; p++) {
        int c = tid + p*256;
        int r = c / 20, seg = c % 20;
        cp16(smem_u32(sV + r*VP + seg*4), Vb + (size_t)(kt + r)*DK + seg*4);
    }
    cp_commit();
}

__global__ __launch_bounds__(256, 2) void attn_kernel()
{
    extern __shared__ float sm[];
    float* sK = sm + A_OFF_K;

    const int b = blockIdx.z, h = blockIdx.y, q0 = blockIdx.x * 128;
    const int tid = threadIdx.x;
    const int warp = tid >> 5, lane = tid & 31;
    const int g = lane >> 2, t = lane & 3;
    const int wr = warp * 16;
    float* sP = sm + A_OFF_P + warp * 16 * PPW;   // warp-private

    const size_t base = ((size_t)b*NH + h) * SS * DK;
    const float* Qb = g_q + base;     // pre-scaled, tf32-rounded
    const float* Kb = g_k + base;
    const float* Vb = g_v + base;

    issueK(Kb, sK, 0, tid);                       // group: K0
    issueV(Vb, sm + A_OFF_V, 0, tid);             // group: V0

    const float* Qr0 = Qb + (size_t)(q0 + wr + g) * DK;
    const float* Qr1 = Qr0 + 8*DK;

    float O[10][4];
    #pragma unroll
    for (int nt = 0; nt < 10; nt++)
        #pragma unroll
        for (int j = 0; j < 4; j++) O[nt][j] = 0.f;
    float m0 = -1e30f, m1 = -1e30f, l0 = 0.f, l1 = 0.f;

    const int pc0 = ((2*t & 3) << 1) | ((2*t) >> 2);
    const int pc1 = (((2*t+1) & 3) << 1) | ((2*t+1) >> 2);

    for (int tt = 0; tt < SS/64; tt++) {
        float* sV = sm + A_OFF_V + (tt & 1) * 64*VP;

        cp_wait<1>();        // K(tt) complete (V(tt) may be pending)
        __syncthreads();

        // ---- scores: Q frags from gmem in 2 batches of 5 k-steps ----
        float sc[8][4];
        #pragma unroll
        for (int nt = 0; nt < 8; nt++)
            #pragma unroll
            for (int j = 0; j < 4; j++) sc[nt][j] = 0.f;

        #pragma unroll
        for (int half = 0; half < 2; half++) {
            unsigned qa[5][4];
            #pragma unroll
            for (int k5 = 0; k5 < 5; k5++) {
                int ks = half*5 + k5;
                qa[k5][0] = __float_as_uint(Qr0[ks*8 + t    ]);
                qa[k5][1] = __float_as_uint(Qr1[ks*8 + t    ]);
                qa[k5][2] = __float_as_uint(Qr0[ks*8 + t + 4]);
                qa[k5][3] = __float_as_uint(Qr1[ks*8 + t + 4]);
            }
            #pragma unroll
            for (int k5 = 0; k5 < 5; k5++) {
                int ks = half*5 + k5;
                #pragma unroll
                for (int nt = 0; nt < 8; nt++) {
                    unsigned bb[2];
                    bb[0] = __float_as_uint(sK[(nt*8 + g)*KP + ks*8 + t    ]);
                    bb[1] = __float_as_uint(sK[(nt*8 + g)*KP + ks*8 + t + 4]);
                    mma_tf32(sc[nt], qa[k5], bb);
                }
            }
        }
        __syncthreads();     // all warps done reading sK
        if (tt + 1 < SS/64)
            issueK(Kb, sK, (tt+1)*64, tid);       // group: K(tt+1)

        // ---- online softmax ----
        float mx0 = -1e30f, mx1 = -1e30f;
        #pragma unroll
        for (int nt = 0; nt < 8; nt++) {
            mx0 = fmaxf(mx0, fmaxf(sc[nt][0], sc[nt][1]));
            mx1 = fmaxf(mx1, fmaxf(sc[nt][2], sc[nt][3]));
        }
        #pragma unroll
        for (int msk = 1; msk <= 2; msk <<= 1) {
            mx0 = fmaxf(mx0, __shfl_xor_sync(0xffffffffu, mx0, msk));
            mx1 = fmaxf(mx1, __shfl_xor_sync(0xffffffffu, mx1, msk));
        }
        float mn0 = fmaxf(m0, mx0), mn1 = fmaxf(m1, mx1);
        float a0 = __expf(m0 - mn0), a1 = __expf(m1 - mn1);
        m0 = mn0; m1 = mn1;

        float sum0 = 0.f, sum1 = 0.f;
        #pragma unroll
        for (int nt = 0; nt < 8; nt++) {
            sc[nt][0] = __expf(sc[nt][0] - m0);
            sc[nt][1] = __expf(sc[nt][1] - m0);
            sc[nt][2] = __expf(sc[nt][2] - m1);
            sc[nt][3] = __expf(sc[nt][3] - m1);
            sum0 += sc[nt][0] + sc[nt][1];
            sum1 += sc[nt][2] + sc[nt][3];
        }
        #pragma unroll
        for (int msk = 1; msk <= 2; msk <<= 1) {
            sum0 += __shfl_xor_sync(0xffffffffu, sum0, msk);
            sum1 += __shfl_xor_sync(0xffffffffu, sum1, msk);
        }
        l0 = l0*a0 + sum0;
        l1 = l1*a1 + sum1;

        #pragma unroll
        for (int nt = 0; nt < 10; nt++) {
            O[nt][0] *= a0; O[nt][1] *= a0;
            O[nt][2] *= a1; O[nt][3] *= a1;
        }

        // ---- stage P (warp-private, rna-rounded, paired cols) ----
        #pragma unroll
        for (int nt = 0; nt < 8; nt++) {
            sP[(g    )*PPW + nt*8 + pc0] = f2tf32(sc[nt][0]);
            sP[(g    )*PPW + nt*8 + pc1] = f2tf32(sc[nt][1]);
            sP[(g + 8)*PPW + nt*8 + pc0] = f2tf32(sc[nt][2]);
            sP[(g + 8)*PPW + nt*8 + pc1] = f2tf32(sc[nt][3]);
        }
        __syncwarp();

        if (tt + 1 < SS/64) cp_wait<1>();   // V(tt) complete (K(tt+1) pending)
        else                cp_wait<0>();   // everything done
        __syncthreads();
        if (tt + 1 < SS/64)
            issueV(Vb, sm + A_OFF_V + ((tt+1)&1)*64*VP, (tt+1)*64, tid);

        // ---- PV: O(16x80) += P(16x64) @ V(64x80) ----
        #pragma unroll
        for (int ks = 0; ks < 8; ks++) {
            float2 plo = *(const float2*)&sP[(g    )*PPW + ks*8 + 2*t];
            float2 phi = *(const float2*)&sP[(g + 8)*PPW + ks*8 + 2*t];
            unsigned pa[4];
            pa[0] = __float_as_uint(plo.x);
            pa[2] = __float_as_uint(plo.y);
            pa[1] = __float_as_uint(phi.x);
            pa[3] = __float_as_uint(phi.y);
            #pragma unroll
            for (int nt = 0; nt < 10; nt++) {
                unsigned bb[2];
                bb[0] = __float_as_uint(sV[(ks*8 + t    )*VP + nt*8 + g]);
                bb[1] = __float_as_uint(sV[(ks*8 + t + 4)*VP + nt*8 + g]);
                mma_tf32(O[nt], pa, bb);
            }
        }
    }

    // ---- epilogue ----
    float inv0 = 1.f / l0, inv1 = 1.f / l1;
    int s0r = q0 + wr + g, s1r = s0r + 8;
    #pragma unroll
    for (int nt = 0; nt < 10; nt++) {
        int c = nt*8 + 2*t;
        float2 v0 = make_float2(O[nt][0]*inv0, O[nt][1]*inv0);
        float2 v1 = make_float2(O[nt][2]*inv1, O[nt][3]*inv1);
        *(float2*)&g_att[((size_t)b*SS + s0r)*DM + h*DK + c] = v0;
        *(float2*)&g_att[((size_t)b*SS + s1r)*DM + h*DK + c] = v1;
    }
}

// ============================================================
// Kernel 3: out = g_att @ Wo^T + bo, bf16 3-term split
// (unchanged from round 5)
// ============================================================
#define GWS 12
#define GBUF (128*GWS)
#define GEMM_SMEM_U32 (8*GBUF)

__global__ __launch_bounds__(256, 2) void out_gemm(
    const float* __restrict__ Wo, const float* __restrict__ bo,
    float* __restrict__ out)
{
    extern __shared__ unsigned gsm[];
    unsigned* AH = gsm;
    unsigned* AL = gsm + 2*GBUF;
    unsigned* BH = gsm + 4*GBUF;
    unsigned* BL = gsm + 6*GBUF;

    const int m0 = blockIdx.y * 128, n0 = blockIdx.x * 128;
    const int tid = threadIdx.x;
    const int warp = tid >> 5, lane = tid & 31;
    const int g = lane >> 2, t = lane & 3;
    const int wm = warp >> 2, wn = warp & 3;

    const int ar0 = tid >> 2, ar1 = (tid + 256) >> 2;
    const int ac = (tid & 3) * 4;
    const int w0 = (tid & 3) * 2;
    const int pw0 = perm8(w0), pw1 = perm8(w0 + 1);

    float acc[4][4][4];
    #pragma unroll
    for (int mt = 0; mt < 4; mt++)
        #pragma unroll
        for (int nt = 0; nt < 4; nt++)
            #pragma unroll
            for (int j = 0; j < 4; j++) acc[mt][nt][j] = 0.f;

    float4 ra[2], rb[2];
    ra[0] = *(const float4*)&g_att[(size_t)(m0 + ar0)*DM + ac];
    ra[1] = *(const float4*)&g_att[(size_t)(m0 + ar1)*DM + ac];
    rb[0] = *(const float4*)&Wo[(size_t)(n0 + ar0)*DM + ac];
    rb[1] = *(const float4*)&Wo[(size_t)(n0 + ar1)*DM + ac];

    for (int kc = 0; kc < DM/16; kc++) {
        const int bs = kc & 1;
        unsigned* ah = AH + bs*GBUF;
        unsigned* al = AL + bs*GBUF;
        unsigned* bh = BH + bs*GBUF;
        unsigned* bl = BL + bs*GBUF;

        #pragma unroll
        for (int p = 0; p < 2; p++) {
            int r = p ? ar1 : ar0;
            float4 va = ra[p], vb = rb[p];
            unsigned ha0 = pack_bf16(va.y, va.x);
            unsigned ha1 = pack_bf16(va.w, va.z);
            unsigned la0 = pack_bf16(va.y - bf_hi(ha0), va.x - bf_lo(ha0));
            unsigned la1 = pack_bf16(va.w - bf_hi(ha1), va.z - bf_lo(ha1));
            ah[r*GWS + pw0] = ha0;  ah[r*GWS + pw1] = ha1;
            al[r*GWS + pw0] = la0;  al[r*GWS + pw1] = la1;
            unsigned hb0 = pack_bf16(vb.y, vb.x);
            unsigned hb1 = pack_bf16(vb.w, vb.z);
            unsigned lb0 = pack_bf16(vb.y - bf_hi(hb0), vb.x - bf_lo(hb0));
            unsigned lb1 = pack_bf16(vb.w - bf_hi(hb1), vb.z - bf_lo(hb1));
            bh[r*GWS + pw0] = hb0;  bh[r*GWS + pw1] = hb1;
            bl[r*GWS + pw0] = lb0;  bl[r*GWS + pw1] = lb1;
        }

        if (kc + 1 < DM/16) {
            int k0n = (kc + 1) * 16;
            ra[0] = *(const float4*)&g_att[(size_t)(m0 + ar0)*DM + k0n + ac];
            ra[1] = *(const float4*)&g_att[(size_t)(m0 + ar1)*DM + k0n + ac];
            rb[0] = *(const float4*)&Wo[(size_t)(n0 + ar0)*DM + k0n + ac];
            rb[1] = *(const float4*)&Wo[(size_t)(n0 + ar1)*DM + k0n + ac];
        }
        __syncthreads();

        unsigned fbh[4][2], fbl[4][2];
        #pragma unroll
        for (int nt = 0; nt < 4; nt++) {
            int br = wn*32 + nt*8 + g;
            uint2 xh = *(const uint2*)&bh[br*GWS + 2*t];
            uint2 xl = *(const uint2*)&bl[br*GWS + 2*t];
            fbh[nt][0] = xh.x; fbh[nt][1] = xh.y;
            fbl[nt][0] = xl.x; fbl[nt][1] = xl.y;
        }
        #pragma unroll
        for (int mt = 0; mt < 4; mt++) {
            int mr = wm*64 + mt*16 + g;
            uint2 alo = *(const uint2*)&ah[ mr     *GWS + 2*t];
            uint2 ahi = *(const uint2*)&ah[(mr + 8)*GWS + 2*t];
            uint2 llo = *(const uint2*)&al[ mr     *GWS + 2*t];
            uint2 lhi = *(const uint2*)&al[(mr + 8)*GWS + 2*t];
            unsigned fah[4] = {alo.x, ahi.x, alo.y, ahi.y};
            unsigned fal[4] = {llo.x, lhi.x, llo.y, lhi.y};
            #pragma unroll
            for (int nt = 0; nt < 4; nt++) {
                mma_bf16(acc[mt][nt], fah, fbh[nt]);
                mma_bf16(acc[mt][nt], fah, fbl[nt]);
                mma_bf16(acc[mt][nt], fal, fbh[nt]);
            }
        }
    }

    #pragma unroll
    for (int mt = 0; mt < 4; mt++) {
        int r0 = m0 + wm*64 + mt*16 + g;
        #pragma unroll
        for (int nt = 0; nt < 4; nt++) {
            int c0 = n0 + wn*32 + nt*8 + 2*t;
            float2 b2 = *(const float2*)&bo[c0];
            float2 v0 = make_float2(acc[mt][nt][0] + b2.x, acc[mt][nt][1] + b2.y);
            float2 v1 = make_float2(acc[mt][nt][2] + b2.x, acc[mt][nt][3] + b2.y);
            *(float2*)&out[(size_t)r0*DM + c0] = v0;
            *(float2*)&out[(size_t)(r0 + 8)*DM + c0] = v1;
        }
    }
}

// ============================================================
extern "C" void kernel_launch(void* const* d_in, const int* in_sizes, int n_in,
                              void* d_out, int out_size)
{
    const float* src = (const float*)d_in[0];
    const float* Wq = (const float*)d_in[3];
    const float* bq = (const float*)d_in[4];
    const float* Wk = (const float*)d_in[5];
    const float* bk = (const float*)d_in[6];
    const float* Wv = (const float*)d_in[7];
    const float* bv = (const float*)d_in[8];
    const float* Wo = (const float*)d_in[9];
    const float* bo = (const float*)d_in[10];
    float* out = (float*)d_out;

    const int smem_qkv  = QKV_SMEM_FLOATS * (int)sizeof(float);
    const int smem_attn = ATTN_SMEM_FLOATS * (int)sizeof(float);
    const int smem_gemm = GEMM_SMEM_U32 * (int)sizeof(unsigned);
    cudaFuncSetAttribute(qkv_kernel, cudaFuncAttributeMaxDynamicSharedMemorySize, smem_qkv);
    cudaFuncSetAttribute(attn_kernel, cudaFuncAttributeMaxDynamicSharedMemorySize, smem_attn);
    cudaFuncSetAttribute(out_gemm, cudaFuncAttributeMaxDynamicSharedMemorySize, smem_gemm);

    qkv_kernel<<<dim3(SS/128, NH, BB), 256, smem_qkv>>>(src, Wq, bq, Wk, bk, Wv, bv);
    attn_kernel<<<dim3(SS/128, NH, BB), 256, smem_attn>>>();
    out_gemm<<<dim3(DM/128, (BB*SS)/128), 256, smem_gemm>>>(Wo, bo, out);
}

// round 8
// speedup vs baseline: 1.2887x; 1.2202x over previous
#include <cuda_runtime.h>
#include <math.h>

#define BB 4
#define SS 1024
#define DM 1280
#define NH 16
#define DK 80
#define GR 5
#define CPG 256

// ---- scratch (device globals; no allocations allowed) ----
__device__ float g_q[(size_t)BB*NH*SS*DK];
__device__ float g_k[(size_t)BB*NH*SS*DK];
__device__ float g_v[(size_t)BB*NH*SS*DK];
// pre-split bf16 words (hi/lo), pre-permuted for m16n8k16 fragments
__device__ unsigned g_ah[(size_t)BB*SS*(DM/2)];
__device__ unsigned g_al[(size_t)BB*SS*(DM/2)];
__device__ unsigned g_bh[(size_t)DM*(DM/2)];
__device__ unsigned g_bl[(size_t)DM*(DM/2)];

// ---- helpers ----
__device__ __forceinline__ float f2tf32(float x) {
    unsigned u;
    asm("cvt.rna.tf32.f32 %0, %1;" : "=r"(u) : "f"(x));
    return __uint_as_float(u);
}
__device__ __forceinline__ void mma_tf32(float d[4], const unsigned a[4], const unsigned b[2]) {
    asm volatile(
        "mma.sync.aligned.m16n8k8.row.col.f32.tf32.tf32.f32 "
        "{%0,%1,%2,%3}, {%4,%5,%6,%7}, {%8,%9}, {%0,%1,%2,%3};\n"
        : "+f"(d[0]), "+f"(d[1]), "+f"(d[2]), "+f"(d[3])
        : "r"(a[0]), "r"(a[1]), "r"(a[2]), "r"(a[3]), "r"(b[0]), "r"(b[1]));
}
__device__ __forceinline__ void mma_bf16(float d[4], const unsigned a[4], const unsigned b[2]) {
    asm volatile(
        "mma.sync.aligned.m16n8k16.row.col.f32.bf16.bf16.f32 "
        "{%0,%1,%2,%3}, {%4,%5,%6,%7}, {%8,%9}, {%0,%1,%2,%3};\n"
        : "+f"(d[0]), "+f"(d[1]), "+f"(d[2]), "+f"(d[3])
        : "r"(a[0]), "r"(a[1]), "r"(a[2]), "r"(a[3]), "r"(b[0]), "r"(b[1]));
}
__device__ __forceinline__ unsigned pack_bf16(float hi, float lo) {
    unsigned r;
    asm("cvt.rn.bf16x2.f32 %0, %1, %2;" : "=r"(r) : "f"(hi), "f"(lo));
    return r;
}
__device__ __forceinline__ float bf_lo(unsigned w) { return __uint_as_float(w << 16); }
__device__ __forceinline__ float bf_hi(unsigned w) { return __uint_as_float(w & 0xffff0000u); }

__device__ __forceinline__ unsigned smem_u32(const void* p) {
    return (unsigned)__cvta_generic_to_shared(p);
}
__device__ __forceinline__ void cp16(unsigned s, const void* g) {
    asm volatile("cp.async.cg.shared.global [%0], [%1], 16;" :: "r"(s), "l"(g));
}
__device__ __forceinline__ void cp_commit() { asm volatile("cp.async.commit_group;"); }
template<int N> __device__ __forceinline__ void cp_wait() {
    asm volatile("cp.async.wait_group %0;" :: "n"(N));
}
// column pairing within 8-group: (t, t+4) -> adjacent (2t, 2t+1)
__device__ __forceinline__ int perm8(int c) {
    return (c & ~7) | ((c & 3) << 1) | ((c >> 2) & 1);
}

// ============================================================
// Kernel 0: pre-split Wo into bf16 hi/lo word arrays, permuted
// so gemm B-fragments load as uint2.
// word w covers k={2w,2w+1}; within each 8-word block, word at
// position perm8(w&7); frag uint2 @ 2t then yields {w=t, w=t+4}.
// ============================================================
__global__ __launch_bounds__(256) void wsplit_kernel(const float* __restrict__ Wo)
{
    int i = blockIdx.x * 256 + threadIdx.x;       // over DM * DM/2 words
    if (i >= DM * (DM/2)) return;
    int n = i / (DM/2), w = i % (DM/2);
    float x0 = Wo[(size_t)n*DM + 2*w];
    float x1 = Wo[(size_t)n*DM + 2*w + 1];
    unsigned h = pack_bf16(x1, x0);
    unsigned l = pack_bf16(x1 - bf_hi(h), x0 - bf_lo(h));
    int pos = (size_t)0 + (w >> 3)*8 + perm8(w & 7);
    g_bh[(size_t)n*(DM/2) + pos] = h;
    g_bl[(size_t)n*(DM/2) + pos] = l;
}

// ============================================================
// Kernel 1: channel shuffle + per-head QKV projections
// (unchanged; 1/sqrt(dk) folded into Wq/bq)
// ============================================================
#define XS 84
#define QKV_SMEM_FLOATS (128*XS + 80*XS + 80)

__global__ __launch_bounds__(256) void qkv_kernel(
    const float* __restrict__ src,
    const float* __restrict__ Wq, const float* __restrict__ bq,
    const float* __restrict__ Wk, const float* __restrict__ bk,
    const float* __restrict__ Wv, const float* __restrict__ bv)
{
    extern __shared__ float qsm[];
    float* sX = qsm;              // [128][84]
    float* sW = sX + 128*XS;      // [80][84]
    float* sb = sW + 80*XS;       // [80]

    const int b = blockIdx.z, h = blockIdx.y, s0 = blockIdx.x * 128;
    const int tid = threadIdx.x;
    const int warp = tid >> 5, lane = tid & 31;
    const int g = lane >> 2, t = lane & 3;
    const int wr = warp * 16;

    #pragma unroll
    for (int p = 0; p < 10; p++) {
        int idx = tid + p*256;
        int r = idx / 20, q = idx % 20;
        int j = q / 4, m = q % 4;
        float4 v = *(const float4*)&src[((size_t)b*SS + s0 + r)*DM + j*CPG + 16*h + m*4];
        int kbase = (m*4)*5 + j;
        sX[r*XS + kbase     ] = f2tf32(v.x);
        sX[r*XS + kbase + 5 ] = f2tf32(v.y);
        sX[r*XS + kbase + 10] = f2tf32(v.z);
        sX[r*XS + kbase + 15] = f2tf32(v.w);
    }
    __syncthreads();

    unsigned qa[10][4];
    #pragma unroll
    for (int ks = 0; ks < 10; ks++) {
        qa[ks][0] = __float_as_uint(sX[(wr + g    )*XS + ks*8 + t    ]);
        qa[ks][1] = __float_as_uint(sX[(wr + g + 8)*XS + ks*8 + t    ]);
        qa[ks][2] = __float_as_uint(sX[(wr + g    )*XS + ks*8 + t + 4]);
        qa[ks][3] = __float_as_uint(sX[(wr + g + 8)*XS + ks*8 + t + 4]);
    }

    const float* Ws[3] = {Wq, Wk, Wv};
    const float* bs[3] = {bq, bk, bv};
    float* outs[3] = {g_q, g_k, g_v};
    const float scl = rsqrtf((float)DK);

    for (int pj = 0; pj < 3; pj++) {
        const float s = (pj == 0) ? scl : 1.f;
        __syncthreads();
        for (int i = tid; i < 1600; i += 256) {
            int e = i / 20, k = (i % 20) * 4;
            float4 w = *(const float4*)&Ws[pj][h*DK*DK + e*DK + k];
            float4 wr4 = make_float4(f2tf32(w.x*s), f2tf32(w.y*s), f2tf32(w.z*s), f2tf32(w.w*s));
            *(float4*)&sW[e*XS + k] = wr4;
        }
        if (tid < DK) sb[tid] = bs[pj][h*DK + tid] * s;
        __syncthreads();

        float acc[10][4];
        #pragma unroll
        for (int nt = 0; nt < 10; nt++)
            #pragma unroll
            for (int j = 0; j < 4; j++) acc[nt][j] = 0.f;

        #pragma unroll
        for (int ks = 0; ks < 10; ks++) {
            #pragma unroll
            for (int nt = 0; nt < 10; nt++) {
                unsigned bb[2];
                bb[0] = __float_as_uint(sW[(nt*8 + g)*XS + ks*8 + t    ]);
                bb[1] = __float_as_uint(sW[(nt*8 + g)*XS + ks*8 + t + 4]);
                mma_tf32(acc[nt], qa[ks], bb);
            }
        }

        float* outp = outs[pj] + (((size_t)b*NH + h)*SS + s0) * DK;
        #pragma unroll
        for (int nt = 0; nt < 10; nt++) {
            int c = nt*8 + 2*t;
            float b0 = sb[c], b1 = sb[c + 1];
            float2 v0 = make_float2(f2tf32(acc[nt][0] + b0), f2tf32(acc[nt][1] + b1));
            float2 v1 = make_float2(f2tf32(acc[nt][2] + b0), f2tf32(acc[nt][3] + b1));
            *(float2*)&outp[(size_t)(wr + g    )*DK + c] = v0;
            *(float2*)&outp[(size_t)(wr + g + 8)*DK + c] = v1;
        }
    }
}

// ============================================================
// Kernel 2: flash attention, tf32 mma
// 256-row q tiles, 8 warps x 32 rows (2 m-tiles/warp):
// K/V B-fragments amortized 2x, 8 warps for latency hiding.
// K single-buffered, V double-buffered, per-warp P.
// Epilogue writes pre-split bf16 hi/lo words (g_ah/g_al).
// ============================================================
#define QP 88
#define KP 84
#define VP 88
#define PPW 72
#define A_OFF_Q 0
#define A_OFF_K (256*QP)
#define A_OFF_V (A_OFF_K + 64*KP)
#define A_OFF_P (A_OFF_V + 2*64*VP)
#define ATTN_SMEM_FLOATS (A_OFF_P + 8*32*PPW)    // 57600 fl = 225 KB

__device__ __forceinline__ void issueK(const float* Kb, float* sK, int kt, int tid)
{
    #pragma unroll
    for (int p = 0; p < 5; p++) {
        int c = tid + p*256;
        int r = c / 20, seg = c % 20;
        cp16(smem_u32(sK + r*KP + seg*4), Kb + (size_t)(kt + r)*DK + seg*4);
    }
    cp_commit();
}
__device__ __forceinline__ void issueV(const float* Vb, float* sV, int kt, int tid)
{
    #pragma unroll
    for (int p = 0; p < 5; p++) {
        int c = tid + p*256;
        int r = c / 20, seg = c % 20;
        cp16(smem_u32(sV + r*VP + seg*4), Vb + (size_t)(kt + r)*DK + seg*4);
    }
    cp_commit();
}

__global__ __launch_bounds__(256) void attn_kernel()
{
    extern __shared__ float sm[];
    float* sQ = sm + A_OFF_Q;
    float* sK = sm + A_OFF_K;

    const int b = blockIdx.z, h = blockIdx.y, q0 = blockIdx.x * 256;
    const int tid = threadIdx.x;
    const int warp = tid >> 5, lane = tid & 31;
    const int g = lane >> 2, t = lane & 3;
    const int wr = warp * 32;
    float* sP = sm + A_OFF_P + warp * 32 * PPW;   // warp-private

    const size_t base = ((size_t)b*NH + h) * SS * DK;
    const float* Qb = g_q + base;     // pre-scaled, tf32-rounded
    const float* Kb = g_k + base;
    const float* Vb = g_v + base;

    // stage Q (column-paired): 256 rows x 80 = 5120 float4 pieces
    #pragma unroll
    for (int p = 0; p < 20; p++) {
        int idx = tid + p*256;
        int r = idx / 20, q4 = idx % 20;
        float4 v = *(const float4*)&Qb[(size_t)(q0 + r)*DK + q4*4];
        int k = q4*4;
        sQ[r*QP + perm8(k    )] = v.x;
        sQ[r*QP + perm8(k + 1)] = v.y;
        sQ[r*QP + perm8(k + 2)] = v.z;
        sQ[r*QP + perm8(k + 3)] = v.w;
    }
    issueK(Kb, sK, 0, tid);                       // group K0
    issueV(Vb, sm + A_OFF_V, 0, tid);             // group V0

    float O[2][10][4];
    #pragma unroll
    for (int mt = 0; mt < 2; mt++)
        #pragma unroll
        for (int nt = 0; nt < 10; nt++)
            #pragma unroll
            for (int j = 0; j < 4; j++) O[mt][nt][j] = 0.f;
    float mM[2][2], lL[2][2];
    #pragma unroll
    for (int mt = 0; mt < 2; mt++) {
        mM[mt][0] = mM[mt][1] = -1e30f;
        lL[mt][0] = lL[mt][1] = 0.f;
    }

    const int pc0 = ((2*t & 3) << 1) | ((2*t) >> 2);
    const int pc1 = (((2*t+1) & 3) << 1) | ((2*t+1) >> 2);

    for (int tt = 0; tt < SS/64; tt++) {
        float* sV = sm + A_OFF_V + (tt & 1) * 64*VP;

        cp_wait<1>();        // K(tt) done (V(tt) may be pending)
        __syncthreads();     // all threads' K shares visible

        // ---- scores: 32x64 per warp, K B-frags shared by 2 m-tiles ----
        float sc[2][8][4];
        #pragma unroll
        for (int mt = 0; mt < 2; mt++)
            #pragma unroll
            for (int nt = 0; nt < 8; nt++)
                #pragma unroll
                for (int j = 0; j < 4; j++) sc[mt][nt][j] = 0.f;

        #pragma unroll
        for (int ks = 0; ks < 10; ks++) {
            unsigned qa2[2][4];
            #pragma unroll
            for (int mt = 0; mt < 2; mt++) {
                float2 qlo = *(const float2*)&sQ[(wr + mt*16 + g    )*QP + ks*8 + 2*t];
                float2 qhi = *(const float2*)&sQ[(wr + mt*16 + g + 8)*QP + ks*8 + 2*t];
                qa2[mt][0] = __float_as_uint(qlo.x);
                qa2[mt][2] = __float_as_uint(qlo.y);
                qa2[mt][1] = __float_as_uint(qhi.x);
                qa2[mt][3] = __float_as_uint(qhi.y);
            }
            #pragma unroll
            for (int nt = 0; nt < 8; nt++) {
                unsigned bb[2];
                bb[0] = __float_as_uint(sK[(nt*8 + g)*KP + ks*8 + t    ]);
                bb[1] = __float_as_uint(sK[(nt*8 + g)*KP + ks*8 + t + 4]);
                mma_tf32(sc[0][nt], qa2[0], bb);
                mma_tf32(sc[1][nt], qa2[1], bb);
            }
        }
        __syncthreads();     // all warps done with sK
        if (tt + 1 < SS/64)
            issueK(Kb, sK, (tt+1)*64, tid);       // group K(tt+1)

        // ---- online softmax + stage P, per m-tile ----
        #pragma unroll
        for (int mt = 0; mt < 2; mt++) {
            float mx0 = -1e30f, mx1 = -1e30f;
            #pragma unroll
            for (int nt = 0; nt < 8; nt++) {
                mx0 = fmaxf(mx0, fmaxf(sc[mt][nt][0], sc[mt][nt][1]));
                mx1 = fmaxf(mx1, fmaxf(sc[mt][nt][2], sc[mt][nt][3]));
            }
            #pragma unroll
            for (int msk = 1; msk <= 2; msk <<= 1) {
                mx0 = fmaxf(mx0, __shfl_xor_sync(0xffffffffu, mx0, msk));
                mx1 = fmaxf(mx1, __shfl_xor_sync(0xffffffffu, mx1, msk));
            }
            float mn0 = fmaxf(mM[mt][0], mx0), mn1 = fmaxf(mM[mt][1], mx1);
            float a0 = __expf(mM[mt][0] - mn0), a1 = __expf(mM[mt][1] - mn1);
            mM[mt][0] = mn0; mM[mt][1] = mn1;

            float sum0 = 0.f, sum1 = 0.f;
            #pragma unroll
            for (int nt = 0; nt < 8; nt++) {
                sc[mt][nt][0] = __expf(sc[mt][nt][0] - mn0);
                sc[mt][nt][1] = __expf(sc[mt][nt][1] - mn0);
                sc[mt][nt][2] = __expf(sc[mt][nt][2] - mn1);
                sc[mt][nt][3] = __expf(sc[mt][nt][3] - mn1);
                sum0 += sc[mt][nt][0] + sc[mt][nt][1];
                sum1 += sc[mt][nt][2] + sc[mt][nt][3];
            }
            #pragma unroll
            for (int msk = 1; msk <= 2; msk <<= 1) {
                sum0 += __shfl_xor_sync(0xffffffffu, sum0, msk);
                sum1 += __shfl_xor_sync(0xffffffffu, sum1, msk);
            }
            lL[mt][0] = lL[mt][0]*a0 + sum0;
            lL[mt][1] = lL[mt][1]*a1 + sum1;

            #pragma unroll
            for (int nt = 0; nt < 10; nt++) {
                O[mt][nt][0] *= a0; O[mt][nt][1] *= a0;
                O[mt][nt][2] *= a1; O[mt][nt][3] *= a1;
            }

            #pragma unroll
            for (int nt = 0; nt < 8; nt++) {
                sP[(mt*16 + g    )*PPW + nt*8 + pc0] = f2tf32(sc[mt][nt][0]);
                sP[(mt*16 + g    )*PPW + nt*8 + pc1] = f2tf32(sc[mt][nt][1]);
                sP[(mt*16 + g + 8)*PPW + nt*8 + pc0] = f2tf32(sc[mt][nt][2]);
                sP[(mt*16 + g + 8)*PPW + nt*8 + pc1] = f2tf32(sc[mt][nt][3]);
            }
        }
        __syncwarp();

        if (tt + 1 < SS/64) cp_wait<1>();   // V(tt) done (K(tt+1) pending)
        else                cp_wait<0>();
        __syncthreads();                    // all threads' V shares visible
        if (tt + 1 < SS/64)
            issueV(Vb, sm + A_OFF_V + ((tt+1)&1)*64*VP, (tt+1)*64, tid);

        // ---- PV: O(32x80) += P(32x64) @ V(64x80), V B-frags shared ----
        #pragma unroll
        for (int ks = 0; ks < 8; ks++) {
            unsigned pa[2][4];
            #pragma unroll
            for (int mt = 0; mt < 2; mt++) {
                float2 plo = *(const float2*)&sP[(mt*16 + g    )*PPW + ks*8 + 2*t];
                float2 phi = *(const float2*)&sP[(mt*16 + g + 8)*PPW + ks*8 + 2*t];
                pa[mt][0] = __float_as_uint(plo.x);
                pa[mt][2] = __float_as_uint(plo.y);
                pa[mt][1] = __float_as_uint(phi.x);
                pa[mt][3] = __float_as_uint(phi.y);
            }
            #pragma unroll
            for (int nt = 0; nt < 10; nt++) {
                unsigned bb[2];
                bb[0] = __float_as_uint(sV[(ks*8 + t    )*VP + nt*8 + g]);
                bb[1] = __float_as_uint(sV[(ks*8 + t + 4)*VP + nt*8 + g]);
                mma_tf32(O[0][nt], pa[0], bb);
                mma_tf32(O[1][nt], pa[1], bb);
            }
        }
    }

    // ---- epilogue: normalize + pre-split bf16 write ----
    #pragma unroll
    for (int mt = 0; mt < 2; mt++) {
        float inv0 = 1.f / lL[mt][0], inv1 = 1.f / lL[mt][1];
        int s0r = q0 + wr + mt*16 + g, s1r = s0r + 8;
        #pragma unroll
        for (int nt = 0; nt < 10; nt++) {
            int w = nt*4 + t;                               // word within head
            int pos = h*(DK/2) + (w >> 3)*8 + perm8(w & 7); // permuted col
            float v00 = O[mt][nt][0]*inv0, v01 = O[mt][nt][1]*inv0;
            float v10 = O[mt][nt][2]*inv1, v11 = O[mt][nt][3]*inv1;
            unsigned h0 = pack_bf16(v01, v00);
            unsigned l0 = pack_bf16(v01 - bf_hi(h0), v00 - bf_lo(h0));
            unsigned h1 = pack_bf16(v11, v10);
            unsigned l1 = pack_bf16(v11 - bf_hi(h1), v10 - bf_lo(h1));
            size_t r0 = ((size_t)b*SS + s0r)*(DM/2) + pos;
            size_t r1 = ((size_t)b*SS + s1r)*(DM/2) + pos;
            g_ah[r0] = h0;  g_al[r0] = l0;
            g_ah[r1] = h1;  g_al[r1] = l1;
        }
    }
}

// ============================================================
// Kernel 3: out = A @ Wo^T + bo from pre-split bf16 words
// cp.async double-buffered, k-chunks of 32 (2 k16 steps)
// row stride 24 words: conflict-free uint2 fragment loads
// ============================================================
#define GS 24
#define GB1 (128*GS)
#define GEMM_SMEM_U32 (8*GB1)     // {AH,AL,BH,BL} x 2 buffers = 96 KB

__device__ __forceinline__ void gemm_issue(unsigned* sbuf, int m0, int n0, int kc, int tid)
{
    const unsigned* srcs[4] = {
        g_ah + (size_t)m0*(DM/2), g_al + (size_t)m0*(DM/2),
        g_bh + (size_t)n0*(DM/2), g_bl + (size_t)n0*(DM/2) };
    #pragma unroll
    for (int a = 0; a < 4; a++) {
        unsigned* dst = sbuf + a*2*GB1;    // buffers interleave below
        #pragma unroll
        for (int p = 0; p < 2; p++) {
            int idx = tid + p*256;
            int r = idx >> 2, seg = idx & 3;
            cp16(smem_u32(dst + r*GS + seg*4),
                 srcs[a] + (size_t)r*(DM/2) + kc*16 + seg*4);
        }
    }
    cp_commit();
}

__global__ __launch_bounds__(256, 2) void out_gemm(
    const float* __restrict__ bo, float* __restrict__ out)
{
    extern __shared__ unsigned gsm[];
    // layout: [AH buf0, AH buf1, AL b0, AL b1, BH b0, BH b1, BL b0, BL b1]

    const int m0 = blockIdx.y * 128, n0 = blockIdx.x * 128;
    const int tid = threadIdx.x;
    const int warp = tid >> 5, lane = tid & 31;
    const int g = lane >> 2, t = lane & 3;
    const int wm = warp >> 2, wn = warp & 3;

    float acc[4][4][4];
    #pragma unroll
    for (int mt = 0; mt < 4; mt++)
        #pragma unroll
        for (int nt = 0; nt < 4; nt++)
            #pragma unroll
            for (int j = 0; j < 4; j++) acc[mt][nt][j] = 0.f;

    gemm_issue(gsm + 0*GB1, m0, n0, 0, tid);
    gemm_issue(gsm + 1*GB1, m0, n0, 1, tid);

    for (int kc = 0; kc < DM/32; kc++) {
        if (kc + 1 < DM/32) cp_wait<1>();
        else                cp_wait<0>();
        __syncthreads();

        const unsigned* AH = gsm + (kc & 1)*GB1;
        const unsigned* AL = AH + 2*GB1;
        const unsigned* BH = AH + 4*GB1;
        const unsigned* BL = AH + 6*GB1;

        #pragma unroll
        for (int kk = 0; kk < 2; kk++) {
            unsigned fbh[4][2], fbl[4][2];
            #pragma unroll
            for (int nt = 0; nt < 4; nt++) {
                int br = wn*32 + nt*8 + g;
                uint2 xh = *(const uint2*)&BH[br*GS + kk*8 + 2*t];
                uint2 xl = *(const uint2*)&BL[br*GS + kk*8 + 2*t];
                fbh[nt][0] = xh.x; fbh[nt][1] = xh.y;
                fbl[nt][0] = xl.x; fbl[nt][1] = xl.y;
            }
            #pragma unroll
            for (int mt = 0; mt < 4; mt++) {
                int mr = wm*64 + mt*16 + g;
                uint2 alo = *(const uint2*)&AH[ mr     *GS + kk*8 + 2*t];
                uint2 ahi = *(const uint2*)&AH[(mr + 8)*GS + kk*8 + 2*t];
                uint2 llo = *(const uint2*)&AL[ mr     *GS + kk*8 + 2*t];
                uint2 lhi = *(const uint2*)&AL[(mr + 8)*GS + kk*8 + 2*t];
                unsigned fah[4] = {alo.x, ahi.x, alo.y, ahi.y};
                unsigned fal[4] = {llo.x, lhi.x, llo.y, lhi.y};
                #pragma unroll
                for (int nt = 0; nt < 4; nt++) {
                    mma_bf16(acc[mt][nt], fah, fbh[nt]);
                    mma_bf16(acc[mt][nt], fah, fbl[nt]);
                    mma_bf16(acc[mt][nt], fal, fbh[nt]);
                }
            }
        }
        __syncthreads();
        if (kc + 2 < DM/32)
            gemm_issue(gsm + (kc & 1)*GB1, m0, n0, kc + 2, tid);
    }

    #pragma unroll
    for (int mt = 0; mt < 4; mt++) {
        int r0 = m0 + wm*64 + mt*16 + g;
        #pragma unroll
        for (int nt = 0; nt < 4; nt++) {
            int c0 = n0 + wn*32 + nt*8 + 2*t;
            float2 b2 = *(const float2*)&bo[c0];
            float2 v0 = make_float2(acc[mt][nt][0] + b2.x, acc[mt][nt][1] + b2.y);
            float2 v1 = make_float2(acc[mt][nt][2] + b2.x, acc[mt][nt][3] + b2.y);
            *(float2*)&out[(size_t)r0*DM + c0] = v0;
            *(float2*)&out[(size_t)(r0 + 8)*DM + c0] = v1;
        }
    }
}

// ============================================================
extern "C" void kernel_launch(void* const* d_in, const int* in_sizes, int n_in,
                              void* d_out, int out_size)
{
    const float* src = (const float*)d_in[0];
    const float* Wq = (const float*)d_in[3];
    const float* bq = (const float*)d_in[4];
    const float* Wk = (const float*)d_in[5];
    const float* bk = (const float*)d_in[6];
    const float* Wv = (const float*)d_in[7];
    const float* bv = (const float*)d_in[8];
    const float* Wo = (const float*)d_in[9];
    const float* bo = (const float*)d_in[10];
    float* out = (float*)d_out;

    const int smem_qkv  = QKV_SMEM_FLOATS * (int)sizeof(float);
    const int smem_attn = ATTN_SMEM_FLOATS * (int)sizeof(float);
    const int smem_gemm = GEMM_SMEM_U32 * (int)sizeof(unsigned);
    cudaFuncSetAttribute(qkv_kernel, cudaFuncAttributeMaxDynamicSharedMemorySize, smem_qkv);
    cudaFuncSetAttribute(attn_kernel, cudaFuncAttributeMaxDynamicSharedMemorySize, smem_attn);
    cudaFuncSetAttribute(out_gemm, cudaFuncAttributeMaxDynamicSharedMemorySize, smem_gemm);

    wsplit_kernel<<<(DM*(DM/2) + 255)/256, 256>>>(Wo);
    qkv_kernel<<<dim3(SS/128, NH, BB), 256, smem_qkv>>>(src, Wq, bq, Wk, bk, Wv, bv);
    attn_kernel<<<dim3(SS/256, NH, BB), 256, smem_attn>>>();
    out_gemm<<<dim3(DM/128, (BB*SS)/128), 256, smem_gemm>>>(bo, out);
}